// round 7
// baseline (speedup 1.0000x reference)
#include <cuda_runtime.h>
#include <cstdint>

#define M_NODES   8192
#define K_PAR     8
#define C_CFG     256
#define N_LAYERS  8
#define TPB       256                          // 8 warps
#define NPT       32                           // nodes per tile
#define TILE_F    (NPT * C_CFG)                // floats per tile (8192)
#define TILE_B    (TILE_F * 4)                 // 32768 bytes
#define NTILES    2                            // tiles per block
#define NBLK      (M_NODES / (NPT * NTILES))   // 128 blocks -> single wave

__device__ __forceinline__ uint32_t smem_u32(const void* p) {
    uint32_t a;
    asm("{ .reg .u64 t; cvta.to.shared.u64 t, %1; cvt.u32.u64 %0, t; }"
        : "=r"(a) : "l"(p));
    return a;
}

__device__ __forceinline__ float fast_tanh(float x) {
    float r;
    asm("tanh.approx.f32 %0, %1;" : "=f"(r) : "f"(x));
    return r;
}

__device__ __forceinline__ float acc_sigmoid(float x) {
    float t = -1.4426950408889634f * x, e, r;
    asm("ex2.approx.f32 %0, %1;" : "=f"(e) : "f"(t));
    float d = 1.0f + e;
    asm("rcp.approx.f32 %0, %1;" : "=f"(r) : "f"(d));
    return r;
}

__device__ __forceinline__ void mbar_wait0(uint32_t mbar_a) {
    uint32_t done;
    asm volatile(
        "{\n\t.reg .pred q;\n\t"
        "mbarrier.try_wait.parity.shared.b64 q, [%1], 0;\n\t"
        "selp.b32 %0, 1, 0, q;\n\t}"
        : "=r"(done) : "r"(mbar_a) : "memory");
    while (!done) {
        asm volatile(
            "{\n\t.reg .pred q;\n\t"
            "mbarrier.try_wait.parity.shared.b64 q, [%1], 0, 1000000;\n\t"
            "selp.b32 %0, 1, 0, q;\n\t}"
            : "=r"(done) : "r"(mbar_a) : "memory");
    }
}

__global__ void root_kernel(const float* __restrict__ root_logits,
                            float* __restrict__ out) {
    int i = blockIdx.x * blockDim.x + threadIdx.x;
    if (i < M_NODES) out[i] = acc_sigmoid(root_logits[i]);
}

// Fold one node-group's tile row. Mapping (validated R2-R6):
//   config c = i*32 + gl*4 + t ; config bit b <-> parent (7-b)
//   t bits 0-1 -> parents 7,6 ; gl bits 2-4 -> parents 5,4,3 (shfl_xor);
//   i bits 5-7 -> parents 2,1,0.
// Folds tanh values (2*sigma - 1); weights sum to 1 per fold, so
// marginal = 0.5 + 0.5 * result.
__device__ __forceinline__ float fold_node(const float* __restrict__ rowbase,
                                           const float* __restrict__ p,
                                           int lane) {
    const int gl = lane & 7;
    const float4* row = reinterpret_cast<const float4*>(rowbase) + gl;
    float r_i[8];
#pragma unroll
    for (int i = 0; i < 8; i++) {
        float4 v = row[i * 8];
        float s0 = fast_tanh(0.5f * v.x);
        float s1 = fast_tanh(0.5f * v.y);
        float s2 = fast_tanh(0.5f * v.z);
        float s3 = fast_tanh(0.5f * v.w);
        float t0 = fmaf(p[7], s1 - s0, s0);
        float t1 = fmaf(p[7], s3 - s2, s2);
        r_i[i]   = fmaf(p[6], t1 - t0, t0);
    }
    float q0 = fmaf(p[2], r_i[1] - r_i[0], r_i[0]);
    float q1 = fmaf(p[2], r_i[3] - r_i[2], r_i[2]);
    float q2 = fmaf(p[2], r_i[5] - r_i[4], r_i[4]);
    float q3 = fmaf(p[2], r_i[7] - r_i[6], r_i[6]);
    float h0 = fmaf(p[1], q1 - q0, q0);
    float h1 = fmaf(p[1], q3 - q2, q2);
    float r  = fmaf(p[0], h1 - h0, h0);
#pragma unroll
    for (int b = 0; b < 3; b++) {
        int   msk = 1 << b;
        float o   = __shfl_xor_sync(0xffffffffu, r, msk);
        float a0  = (lane & msk) ? o : r;
        float a1  = (lane & msk) ? r : o;
        r = fmaf(p[5 - b], a1 - a0, a0);
    }
    return r;
}

// 128 blocks (single wave), 256 threads, 64 nodes per block as 2 x 32-node
// tiles. Both TMA bulk copies issued at block start -> the entire 8MB layer
// is in flight immediately; compute overlaps delivery.
__global__ void __launch_bounds__(TPB)
layer_kernel(const float* __restrict__ cpt,     // [M, C]
             const int*   __restrict__ parents, // [M, K]
             const float* __restrict__ prev,    // [M]
             float*       __restrict__ out)     // [M]
{
    extern __shared__ __align__(16) float tile[];   // 2 * TILE_F floats
    __shared__ __align__(8) uint64_t mbar[NTILES];

    const int tid    = threadIdx.x;
    const int lane   = tid & 31;
    const int wid    = tid >> 5;
    const int nloc   = wid * 4 + (lane >> 3);       // node within tile (0..31)
    const int pbase  = lane & 24;
    const int nbase  = blockIdx.x * (NPT * NTILES); // first node of this block

    if (tid == 0) {
#pragma unroll
        for (int t = 0; t < NTILES; t++) {
            const uint32_t ma = smem_u32(&mbar[t]);
            asm volatile("mbarrier.init.shared.b64 [%0], 1;" :: "r"(ma) : "memory");
        }
        asm volatile("fence.proxy.async.shared::cta;" ::: "memory");
#pragma unroll
        for (int t = 0; t < NTILES; t++) {
            const uint32_t ma = smem_u32(&mbar[t]);
            asm volatile("mbarrier.arrive.expect_tx.shared.b64 _, [%0], %1;"
                         :: "r"(ma), "r"((uint32_t)TILE_B) : "memory");
            asm volatile(
                "cp.async.bulk.shared::cta.global.mbarrier::complete_tx::bytes "
                "[%0], [%1], %2, [%3];"
                :: "r"(smem_u32(tile + t * TILE_F)),
                   "l"(cpt + (size_t)(nbase + t * NPT) * C_CFG),
                   "r"((uint32_t)TILE_B), "r"(ma)
                : "memory");
        }
    }
    __syncthreads();   // mbarrier init visible to all waiters

    // Parent gathers for BOTH tiles overlap the TMA transfers.
    // parents[(nbase + t*NPT)*8 + tid] covers node (nbase+t*NPT + wid*4+(lane>>3)),
    // parent (lane&7) -- coalesced.
    const int   pidx0 = parents[nbase * K_PAR + tid];
    const int   pidx1 = parents[(nbase + NPT) * K_PAR + tid];
    const float pp0   = prev[pidx0];
    const float pp1   = prev[pidx1];

    float p[8];

    // ---- tile 0
#pragma unroll
    for (int j = 0; j < 8; j++)
        p[j] = __shfl_sync(0xffffffffu, pp0, pbase | j);
    mbar_wait0(smem_u32(&mbar[0]));
    {
        float r = fold_node(tile + nloc * C_CFG, p, lane);
        if ((lane & 7) == 0) out[nbase + nloc] = fmaf(0.5f, r, 0.5f);
    }

    // ---- tile 1
#pragma unroll
    for (int j = 0; j < 8; j++)
        p[j] = __shfl_sync(0xffffffffu, pp1, pbase | j);
    mbar_wait0(smem_u32(&mbar[1]));
    {
        float r = fold_node(tile + TILE_F + nloc * C_CFG, p, lane);
        if ((lane & 7) == 0) out[nbase + NPT + nloc] = fmaf(0.5f, r, 0.5f);
    }
}

extern "C" void kernel_launch(void* const* d_in, const int* in_sizes, int n_in,
                              void* d_out, int out_size) {
    const float* root    = (const float*)d_in[0];  // [M]
    const float* cpt     = (const float*)d_in[1];  // [L, M, C]
    const int*   parents = (const int*)  d_in[2];  // [L, M, K]
    float*       out     = (float*)d_out;          // [(L+1)*M]

    static const size_t SMEM_DYN = NTILES * TILE_B;   // 64 KB
    cudaFuncSetAttribute(layer_kernel,
                         cudaFuncAttributeMaxDynamicSharedMemorySize,
                         (int)SMEM_DYN);

    root_kernel<<<M_NODES / 256, 256>>>(root, out);

    for (int l = 0; l < N_LAYERS; l++) {
        layer_kernel<<<NBLK, TPB, SMEM_DYN>>>(
            cpt     + (size_t)l * M_NODES * C_CFG,
            parents + (size_t)l * M_NODES * K_PAR,
            out     + (size_t)l * M_NODES,
            out     + (size_t)(l + 1) * M_NODES);
    }
}

// round 9
// speedup vs baseline: 1.0022x; 1.0022x over previous
#include <cuda_runtime.h>
#include <cstdint>

#define M_NODES   8192
#define K_PAR     8
#define C_CFG     256
#define N_LAYERS  8
#define TPB       256                          // 8 warps
#define NPB       64                           // nodes per block
#define TILE_F    (NPB * C_CFG)                // 16384 floats
#define TILE_B    (TILE_F * 4)                 // 65536 bytes
#define NBLK      (M_NODES / NPB)              // 128 blocks per layer

__device__ unsigned int g_done[N_LAYERS];      // blocks finished per layer

__device__ __forceinline__ uint32_t smem_u32(const void* p) {
    uint32_t a;
    asm("{ .reg .u64 t; cvta.to.shared.u64 t, %1; cvt.u32.u64 %0, t; }"
        : "=r"(a) : "l"(p));
    return a;
}

__device__ __forceinline__ float fast_tanh(float x) {
    float r;
    asm("tanh.approx.f32 %0, %1;" : "=f"(r) : "f"(x));
    return r;
}

__device__ __forceinline__ float acc_sigmoid(float x) {
    float t = -1.4426950408889634f * x, e, r;
    asm("ex2.approx.f32 %0, %1;" : "=f"(e) : "f"(t));
    float d = 1.0f + e;
    asm("rcp.approx.f32 %0, %1;" : "=f"(r) : "f"(d));
    return r;
}

__device__ __forceinline__ void mbar_wait0(uint32_t mbar_a) {
    uint32_t done;
    asm volatile(
        "{\n\t.reg .pred q;\n\t"
        "mbarrier.try_wait.parity.shared.b64 q, [%1], 0;\n\t"
        "selp.b32 %0, 1, 0, q;\n\t}"
        : "=r"(done) : "r"(mbar_a) : "memory");
    while (!done) {
        asm volatile(
            "{\n\t.reg .pred q;\n\t"
            "mbarrier.try_wait.parity.shared.b64 q, [%1], 0, 1000000;\n\t"
            "selp.b32 %0, 1, 0, q;\n\t}"
            : "=r"(done) : "r"(mbar_a) : "memory");
    }
}

// Root: resets handoff counters (safe: replays are graph-serialized, and all
// layer grids launch only after root's implicit trigger = root completion),
// then computes root marginals. NO explicit trigger -> all writes pre-trigger.
__global__ void __launch_bounds__(256)
root_kernel(const float* __restrict__ root_logits, float* __restrict__ out) {
    if (blockIdx.x == 0 && threadIdx.x < N_LAYERS)
        g_done[threadIdx.x] = 0;
    int i = blockIdx.x * 256 + threadIdx.x;
    if (i < M_NODES) out[i] = acc_sigmoid(root_logits[i]);
}

// Fold pre-tanh'd values. Mapping (validated R2-R7):
//   config c = i*32 + gl*4 + t ; config bit b <-> parent (7-b)
//   t bits 0-1 -> parents 7,6 ; gl bits 2-4 -> parents 5,4,3 (shfl_xor);
//   i bits 5-7 -> parents 2,1,0.  marginal = 0.5 + 0.5 * result.
__device__ __forceinline__ float fold_node(const float* __restrict__ rowbase,
                                           const float* __restrict__ p,
                                           int lane) {
    const float4* row = reinterpret_cast<const float4*>(rowbase) + (lane & 7);
    float r_i[8];
#pragma unroll
    for (int i = 0; i < 8; i++) {
        float4 v = row[i * 8];
        float t0 = fmaf(p[7], v.y - v.x, v.x);
        float t1 = fmaf(p[7], v.w - v.z, v.z);
        r_i[i]   = fmaf(p[6], t1 - t0, t0);
    }
    float q0 = fmaf(p[2], r_i[1] - r_i[0], r_i[0]);
    float q1 = fmaf(p[2], r_i[3] - r_i[2], r_i[2]);
    float q2 = fmaf(p[2], r_i[5] - r_i[4], r_i[4]);
    float q3 = fmaf(p[2], r_i[7] - r_i[6], r_i[6]);
    float h0 = fmaf(p[1], q1 - q0, q0);
    float h1 = fmaf(p[1], q3 - q2, q2);
    float r  = fmaf(p[0], h1 - h0, h0);
#pragma unroll
    for (int b = 0; b < 3; b++) {
        int   msk = 1 << b;
        float o   = __shfl_xor_sync(0xffffffffu, r, msk);
        float a0  = (lane & msk) ? o : r;
        float a1  = (lane & msk) ? r : o;
        r = fmaf(p[5 - b], a1 - a0, a0);
    }
    return r;
}

// PDL cascade kernel. Trigger fires in the prologue so the next layer's grid
// launches immediately and runs its prologue (TMA + tanh) concurrently.
// Cross-layer DATA handoff uses release/acquire counters, NOT the PDL edge.
__global__ void __launch_bounds__(TPB)
layer_kernel(int layer,
             const float* __restrict__ cpt,     // [M, C]
             const int*   __restrict__ parents, // [M, K]
             const float* __restrict__ prev,    // [M]
             float*       __restrict__ out)     // [M]
{
    extern __shared__ __align__(16) float tile[];   // TILE_F floats (64 KB)
    __shared__ __align__(8) uint64_t mbar;

    const int tid   = threadIdx.x;
    const int lane  = tid & 31;
    const int wid   = tid >> 5;
    const int nloc  = wid * 4 + (lane >> 3);        // 0..31 within half-tile
    const int pbase = lane & 24;
    const int nbase = blockIdx.x * NPB;

    const uint32_t mbar_a = smem_u32(&mbar);
    if (tid == 0) {
        asm volatile("mbarrier.init.shared.b64 [%0], 1;" :: "r"(mbar_a) : "memory");
        asm volatile("fence.proxy.async.shared::cta;" ::: "memory");
        asm volatile("mbarrier.arrive.expect_tx.shared.b64 _, [%0], %1;"
                     :: "r"(mbar_a), "r"((uint32_t)TILE_B) : "memory");
        asm volatile(
            "cp.async.bulk.shared::cta.global.mbarrier::complete_tx::bytes "
            "[%0], [%1], %2, [%3];"
            :: "r"(smem_u32(tile)),
               "l"(cpt + (size_t)nbase * C_CFG),
               "r"((uint32_t)TILE_B), "r"(mbar_a)
            : "memory");
    }

    // Prev-independent loads.
    const int pidx0 = parents[nbase * K_PAR + tid];          // nodes 0..31
    const int pidx1 = parents[nbase * K_PAR + TPB + tid];    // nodes 32..63

    // Cascade the next layer's launch NOW (data handoff is via g_done).
    cudaTriggerProgrammaticLaunchCompletion();

    __syncthreads();                 // mbarrier init visible
    mbar_wait0(mbar_a);

    // tanh pass in smem (prev-independent MUFU bulk): tile <- tanh(0.5*x).
    float4* t4 = reinterpret_cast<float4*>(tile);
#pragma unroll
    for (int k = 0; k < TILE_F / 4 / TPB; k++) {
        float4 v = t4[tid + k * TPB];
        v.x = fast_tanh(0.5f * v.x);
        v.y = fast_tanh(0.5f * v.y);
        v.z = fast_tanh(0.5f * v.z);
        v.w = fast_tanh(0.5f * v.w);
        t4[tid + k * TPB] = v;
    }

    // Wait until the previous layer's marginals are ready.
    if (layer == 0) {
        cudaGridDependencySynchronize();   // root: implicit trigger at exit
        __syncthreads();                   // (also orders the tanh pass)
    } else {
        __syncthreads();                   // tanh pass done before spin/exit
        if (tid == 0) {
            unsigned v;
            do {
                asm volatile("ld.acquire.gpu.global.u32 %0, [%1];"
                             : "=r"(v) : "l"(&g_done[layer - 1]) : "memory");
                if (v >= NBLK) break;
                __nanosleep(128);
            } while (true);
        }
        __syncthreads();                   // acquire visible block-wide
    }

    const float pp0 = prev[pidx0];
    const float pp1 = prev[pidx1];

    float p[8];
#pragma unroll
    for (int j = 0; j < 8; j++)
        p[j] = __shfl_sync(0xffffffffu, pp0, pbase | j);
    {
        float r = fold_node(tile + nloc * C_CFG, p, lane);
        if ((lane & 7) == 0) out[nbase + nloc] = fmaf(0.5f, r, 0.5f);
    }

#pragma unroll
    for (int j = 0; j < 8; j++)
        p[j] = __shfl_sync(0xffffffffu, pp1, pbase | j);
    {
        float r = fold_node(tile + (32 + nloc) * C_CFG, p, lane);
        if ((lane & 7) == 0) out[nbase + 32 + nloc] = fmaf(0.5f, r, 0.5f);
    }

    // Release this block's outputs to the next layer.
    __syncthreads();
    if (tid == 0) {
        __threadfence();
        atomicAdd(&g_done[layer], 1u);
    }
}

extern "C" void kernel_launch(void* const* d_in, const int* in_sizes, int n_in,
                              void* d_out, int out_size) {
    const float* root    = (const float*)d_in[0];  // [M]
    const float* cpt     = (const float*)d_in[1];  // [L, M, C]
    const int*   parents = (const int*)  d_in[2];  // [L, M, K]
    float*       out     = (float*)d_out;          // [(L+1)*M]

    cudaFuncSetAttribute(layer_kernel,
                         cudaFuncAttributeMaxDynamicSharedMemorySize, TILE_B);

    root_kernel<<<M_NODES / 256, 256>>>(root, out);

    cudaLaunchAttribute attr[1];
    attr[0].id = cudaLaunchAttributeProgrammaticStreamSerialization;
    attr[0].val.programmaticStreamSerializationAllowed = 1;

    for (int l = 0; l < N_LAYERS; l++) {
        cudaLaunchConfig_t cfg = {};
        cfg.gridDim          = dim3(NBLK, 1, 1);
        cfg.blockDim         = dim3(TPB, 1, 1);
        cfg.dynamicSmemBytes = TILE_B;
        cfg.stream           = 0;
        cfg.attrs            = attr;
        cfg.numAttrs         = 1;
        const float* cpt_l  = cpt     + (size_t)l * M_NODES * C_CFG;
        const int*   par_l  = parents + (size_t)l * M_NODES * K_PAR;
        const float* prev_l = out     + (size_t)l * M_NODES;
        float*       out_l  = out     + (size_t)(l + 1) * M_NODES;
        cudaLaunchKernelEx(&cfg, layer_kernel, l, cpt_l, par_l, prev_l, out_l);
    }
}

// round 10
// speedup vs baseline: 1.0849x; 1.0825x over previous
#include <cuda_runtime.h>
#include <cstdint>

#define M_NODES   8192
#define K_PAR     8
#define C_CFG     256
#define N_LAYERS  8
#define TPB       256                          // 8 warps
#define NPB       64                           // nodes per block per layer
#define TILE_F    (NPB * C_CFG)                // 16384 floats
#define TILE_B    (TILE_F * 4)                 // 65536 bytes
#define NBLK      (M_NODES / NPB)              // 128 blocks (1/SM, co-resident)

__device__ unsigned int g_done[N_LAYERS + 1];  // [0]=root ready .. [8]=all done

__device__ __forceinline__ uint32_t smem_u32(const void* p) {
    uint32_t a;
    asm("{ .reg .u64 t; cvta.to.shared.u64 t, %1; cvt.u32.u64 %0, t; }"
        : "=r"(a) : "l"(p));
    return a;
}

__device__ __forceinline__ float fast_tanh(float x) {
    float r;
    asm("tanh.approx.f32 %0, %1;" : "=f"(r) : "f"(x));
    return r;
}

__device__ __forceinline__ float acc_sigmoid(float x) {
    float t = -1.4426950408889634f * x, e, r;
    asm("ex2.approx.f32 %0, %1;" : "=f"(e) : "f"(t));
    float d = 1.0f + e;
    asm("rcp.approx.f32 %0, %1;" : "=f"(r) : "f"(d));
    return r;
}

__device__ __forceinline__ void mbar_wait(uint32_t mbar_a, uint32_t parity) {
    uint32_t done;
    asm volatile(
        "{\n\t.reg .pred q;\n\t"
        "mbarrier.try_wait.parity.shared.b64 q, [%1], %2;\n\t"
        "selp.b32 %0, 1, 0, q;\n\t}"
        : "=r"(done) : "r"(mbar_a), "r"(parity) : "memory");
    while (!done) {
        asm volatile(
            "{\n\t.reg .pred q;\n\t"
            "mbarrier.try_wait.parity.shared.b64 q, [%1], %2, 1000000;\n\t"
            "selp.b32 %0, 1, 0, q;\n\t}"
            : "=r"(done) : "r"(mbar_a), "r"(parity) : "memory");
    }
}

__device__ __forceinline__ void tma_tile(uint32_t smem_dst, const float* gsrc,
                                         uint32_t mbar_a) {
    asm volatile("mbarrier.arrive.expect_tx.shared.b64 _, [%0], %1;"
                 :: "r"(mbar_a), "r"((uint32_t)TILE_B) : "memory");
    asm volatile(
        "cp.async.bulk.shared::cta.global.mbarrier::complete_tx::bytes "
        "[%0], [%1], %2, [%3];"
        :: "r"(smem_dst), "l"(gsrc), "r"((uint32_t)TILE_B), "r"(mbar_a)
        : "memory");
}

// Fold pre-tanh'd tile row. Mapping (validated R2-R9):
//   config c = i*32 + gl*4 + t ; config bit b <-> parent (7-b)
//   t bits 0-1 -> parents 7,6 ; gl bits 2-4 -> parents 5,4,3 (shfl_xor);
//   i bits 5-7 -> parents 2,1,0.  marginal = 0.5 + 0.5 * result.
__device__ __forceinline__ float fold_node(const float* __restrict__ rowbase,
                                           const float* __restrict__ p,
                                           int lane) {
    const float4* row = reinterpret_cast<const float4*>(rowbase) + (lane & 7);
    float r_i[8];
#pragma unroll
    for (int i = 0; i < 8; i++) {
        float4 v = row[i * 8];
        float t0 = fmaf(p[7], v.y - v.x, v.x);
        float t1 = fmaf(p[7], v.w - v.z, v.z);
        r_i[i]   = fmaf(p[6], t1 - t0, t0);
    }
    float q0 = fmaf(p[2], r_i[1] - r_i[0], r_i[0]);
    float q1 = fmaf(p[2], r_i[3] - r_i[2], r_i[2]);
    float q2 = fmaf(p[2], r_i[5] - r_i[4], r_i[4]);
    float q3 = fmaf(p[2], r_i[7] - r_i[6], r_i[6]);
    float h0 = fmaf(p[1], q1 - q0, q0);
    float h1 = fmaf(p[1], q3 - q2, q2);
    float r  = fmaf(p[0], h1 - h0, h0);
#pragma unroll
    for (int b = 0; b < 3; b++) {
        int   msk = 1 << b;
        float o   = __shfl_xor_sync(0xffffffffu, r, msk);
        float a0  = (lane & msk) ? o : r;
        float a1  = (lane & msk) ? r : o;
        r = fmaf(p[5 - b], a1 - a0, a0);
    }
    return r;
}

__global__ void __launch_bounds__(TPB)
persist_kernel(const float* __restrict__ root,
               const float* __restrict__ cpt,      // [L, M, C]
               const int*   __restrict__ parents,  // [L, M, K]
               float*       __restrict__ out)      // [(L+1)*M]
{
    extern __shared__ __align__(16) float buf[];   // 2 * TILE_F floats (128 KB)
    __shared__ __align__(8) uint64_t mbar[2];

    const int tid   = threadIdx.x;
    const int lane  = tid & 31;
    const int wid   = tid >> 5;
    const int nloc  = wid * 4 + (lane >> 3);       // 0..31 within half-tile
    const int pbase = lane & 24;
    const int nbase = blockIdx.x * NPB;

    const uint32_t mb0 = smem_u32(&mbar[0]);
    const uint32_t mb1 = smem_u32(&mbar[1]);

    if (tid == 0) {
        asm volatile("mbarrier.init.shared.b64 [%0], 1;" :: "r"(mb0) : "memory");
        asm volatile("mbarrier.init.shared.b64 [%0], 1;" :: "r"(mb1) : "memory");
        asm volatile("fence.proxy.async.shared::cta;" ::: "memory");
        // Prefetch layer 0 and layer 1 tiles immediately.
        tma_tile(smem_u32(buf),          cpt + (size_t)nbase * C_CFG,            mb0);
        tma_tile(smem_u32(buf + TILE_F), cpt + (size_t)(M_NODES + nbase) * C_CFG, mb1);
    }

    // Root marginals: this block's 64 roots (independent of everything).
    if (tid < NPB)
        out[nbase + tid] = acc_sigmoid(root[nbase + tid]);
    __syncthreads();   // roots stored + mbarrier init visible
    if (tid == 0) {
        __threadfence();
        atomicAdd(&g_done[0], 1u);
    }

#pragma unroll 1
    for (int l = 0; l < N_LAYERS; l++) {
        float* tb = buf + (l & 1) * TILE_F;
        const uint32_t mb = (l & 1) ? mb1 : mb0;

        // Parent indices (coalesced; latency hidden under tanh pass below).
        const size_t pofs = (size_t)l * M_NODES * K_PAR + (size_t)nbase * K_PAR;
        const int pidx0 = parents[pofs + tid];
        const int pidx1 = parents[pofs + TPB + tid];

        // Wait for this layer's CPT tile.
        mbar_wait(mb, (l >> 1) & 1);

        // tanh pass (prev-independent; off the serial chain).
        float4* t4 = reinterpret_cast<float4*>(tb);
#pragma unroll
        for (int k = 0; k < TILE_F / 4 / TPB; k++) {
            float4 v = t4[tid + k * TPB];
            v.x = fast_tanh(0.5f * v.x);
            v.y = fast_tanh(0.5f * v.y);
            v.z = fast_tanh(0.5f * v.z);
            v.w = fast_tanh(0.5f * v.w);
            t4[tid + k * TPB] = v;
        }
        __syncthreads();   // tanh results visible to fold

        // Wait for previous layer's marginals (release/acquire handoff).
        if (tid == 0) {
            unsigned v;
            do {
                asm volatile("ld.acquire.gpu.global.u32 %0, [%1];"
                             : "=r"(v) : "l"(&g_done[l]) : "memory");
                if (v >= NBLK) break;
                __nanosleep(64);
            } while (true);
        }
        __syncthreads();

        const float* prev = out + (size_t)l * M_NODES;
        float*       dst  = out + (size_t)(l + 1) * M_NODES;
        const float pp0 = prev[pidx0];
        const float pp1 = prev[pidx1];

        float p[8];
#pragma unroll
        for (int j = 0; j < 8; j++)
            p[j] = __shfl_sync(0xffffffffu, pp0, pbase | j);
        {
            float r = fold_node(tb + nloc * C_CFG, p, lane);
            if ((lane & 7) == 0) dst[nbase + nloc] = fmaf(0.5f, r, 0.5f);
        }
#pragma unroll
        for (int j = 0; j < 8; j++)
            p[j] = __shfl_sync(0xffffffffu, pp1, pbase | j);
        {
            float r = fold_node(tb + (32 + nloc) * C_CFG, p, lane);
            if ((lane & 7) == 0) dst[nbase + 32 + nloc] = fmaf(0.5f, r, 0.5f);
        }

        __syncthreads();   // folds done (buffer free) + stores issued
        if (tid == 0) {
            __threadfence();
            atomicAdd(&g_done[l + 1], 1u);      // release outputs
            // Refill the freed buffer with layer l+2's tile.
            if (l + 2 < N_LAYERS)
                tma_tile(smem_u32(tb),
                         cpt + ((size_t)(l + 2) * M_NODES + nbase) * C_CFG, mb);
        }
    }

    // Replay-safe counter reset: ordered after every block's fenced signals.
    if (blockIdx.x == 0 && tid == 0) {
        unsigned v;
        do {
            asm volatile("ld.acquire.gpu.global.u32 %0, [%1];"
                         : "=r"(v) : "l"(&g_done[N_LAYERS]) : "memory");
            if (v >= NBLK) break;
            __nanosleep(64);
        } while (true);
#pragma unroll
        for (int i = 0; i <= N_LAYERS; i++)
            g_done[i] = 0;
        __threadfence();
    }
}

extern "C" void kernel_launch(void* const* d_in, const int* in_sizes, int n_in,
                              void* d_out, int out_size) {
    const float* root    = (const float*)d_in[0];  // [M]
    const float* cpt     = (const float*)d_in[1];  // [L, M, C]
    const int*   parents = (const int*)  d_in[2];  // [L, M, K]
    float*       out     = (float*)d_out;          // [(L+1)*M]

    static const int SMEM_DYN = 2 * TILE_B;        // 128 KB
    cudaFuncSetAttribute(persist_kernel,
                         cudaFuncAttributeMaxDynamicSharedMemorySize, SMEM_DYN);

    persist_kernel<<<NBLK, TPB, SMEM_DYN>>>(root, cpt, parents, out);
}

// round 11
// speedup vs baseline: 1.1750x; 1.0830x over previous
#include <cuda_runtime.h>
#include <cstdint>

#define M_NODES   8192
#define K_PAR     8
#define C_CFG     256
#define N_LAYERS  8
#define TPB       512                          // 16 warps
#define NPB       64                           // nodes per block per layer
#define TILE_F    (NPB * C_CFG)                // 16384 floats
#define TILE_B    (TILE_F * 4)                 // 65536 bytes
#define NBLK      (M_NODES / NPB)              // 128 blocks (1/SM, co-resident)

__device__ unsigned int g_done[N_LAYERS + 1];  // [0]=roots ready .. [8]=all done

__device__ __forceinline__ uint32_t smem_u32(const void* p) {
    uint32_t a;
    asm("{ .reg .u64 t; cvta.to.shared.u64 t, %1; cvt.u32.u64 %0, t; }"
        : "=r"(a) : "l"(p));
    return a;
}

__device__ __forceinline__ float fast_tanh(float x) {
    float r;
    asm("tanh.approx.f32 %0, %1;" : "=f"(r) : "f"(x));
    return r;
}

__device__ __forceinline__ float acc_sigmoid(float x) {
    float t = -1.4426950408889634f * x, e, r;
    asm("ex2.approx.f32 %0, %1;" : "=f"(e) : "f"(t));
    float d = 1.0f + e;
    asm("rcp.approx.f32 %0, %1;" : "=f"(r) : "f"(d));
    return r;
}

__device__ __forceinline__ void mbar_wait(uint32_t mbar_a, uint32_t parity) {
    uint32_t done;
    asm volatile(
        "{\n\t.reg .pred q;\n\t"
        "mbarrier.try_wait.parity.shared.b64 q, [%1], %2;\n\t"
        "selp.b32 %0, 1, 0, q;\n\t}"
        : "=r"(done) : "r"(mbar_a), "r"(parity) : "memory");
    while (!done) {
        asm volatile(
            "{\n\t.reg .pred q;\n\t"
            "mbarrier.try_wait.parity.shared.b64 q, [%1], %2, 1000000;\n\t"
            "selp.b32 %0, 1, 0, q;\n\t}"
            : "=r"(done) : "r"(mbar_a), "r"(parity) : "memory");
    }
}

__device__ __forceinline__ void tma_tile(uint32_t smem_dst, const float* gsrc,
                                         uint32_t mbar_a) {
    asm volatile("mbarrier.arrive.expect_tx.shared.b64 _, [%0], %1;"
                 :: "r"(mbar_a), "r"((uint32_t)TILE_B) : "memory");
    asm volatile(
        "cp.async.bulk.shared::cta.global.mbarrier::complete_tx::bytes "
        "[%0], [%1], %2, [%3];"
        :: "r"(smem_dst), "l"(gsrc), "r"((uint32_t)TILE_B), "r"(mbar_a)
        : "memory");
}

// Fold with INLINE tanh. Mapping (validated R2-R10):
//   config c = i*32 + gl*4 + t ; config bit b <-> parent (7-b)
//   t bits 0-1 -> parents 7,6 ; gl bits 2-4 -> parents 5,4,3 (shfl_xor);
//   i bits 5-7 -> parents 2,1,0.  marginal = 0.5 + 0.5 * result.
__device__ __forceinline__ float fold_node(const float* __restrict__ rowbase,
                                           const float* __restrict__ p,
                                           int lane) {
    const float4* row = reinterpret_cast<const float4*>(rowbase) + (lane & 7);
    float r_i[8];
#pragma unroll
    for (int i = 0; i < 8; i++) {
        float4 v = row[i * 8];
        float s0 = fast_tanh(0.5f * v.x);
        float s1 = fast_tanh(0.5f * v.y);
        float s2 = fast_tanh(0.5f * v.z);
        float s3 = fast_tanh(0.5f * v.w);
        float t0 = fmaf(p[7], s1 - s0, s0);
        float t1 = fmaf(p[7], s3 - s2, s2);
        r_i[i]   = fmaf(p[6], t1 - t0, t0);
    }
    float q0 = fmaf(p[2], r_i[1] - r_i[0], r_i[0]);
    float q1 = fmaf(p[2], r_i[3] - r_i[2], r_i[2]);
    float q2 = fmaf(p[2], r_i[5] - r_i[4], r_i[4]);
    float q3 = fmaf(p[2], r_i[7] - r_i[6], r_i[6]);
    float h0 = fmaf(p[1], q1 - q0, q0);
    float h1 = fmaf(p[1], q3 - q2, q2);
    float r  = fmaf(p[0], h1 - h0, h0);
#pragma unroll
    for (int b = 0; b < 3; b++) {
        int   msk = 1 << b;
        float o   = __shfl_xor_sync(0xffffffffu, r, msk);
        float a0  = (lane & msk) ? o : r;
        float a1  = (lane & msk) ? r : o;
        r = fmaf(p[5 - b], a1 - a0, a0);
    }
    return r;
}

__global__ void __launch_bounds__(TPB)
persist_kernel(const float* __restrict__ root,
               const float* __restrict__ cpt,      // [L, M, C]
               const int*   __restrict__ parents,  // [L, M, K]
               float*       __restrict__ out)      // [(L+1)*M]
{
    extern __shared__ __align__(16) float buf[];   // 2 * TILE_F floats (128 KB)
    __shared__ __align__(8) uint64_t mbar[2];

    const int tid   = threadIdx.x;
    const int lane  = tid & 31;
    const int wid   = tid >> 5;                    // 0..15
    const int nloc  = wid * 4 + (lane >> 3);       // 0..63: this lane's node
    const int pbase = lane & 24;
    const int nbase = blockIdx.x * NPB;

    const uint32_t mb0 = smem_u32(&mbar[0]);
    const uint32_t mb1 = smem_u32(&mbar[1]);

    if (tid == 0) {
        asm volatile("mbarrier.init.shared.b64 [%0], 1;" :: "r"(mb0) : "memory");
        asm volatile("mbarrier.init.shared.b64 [%0], 1;" :: "r"(mb1) : "memory");
        asm volatile("fence.proxy.async.shared::cta;" ::: "memory");
        // Prefetch layer 0 and layer 1 tiles immediately.
        tma_tile(smem_u32(buf),          cpt + (size_t)nbase * C_CFG,             mb0);
        tma_tile(smem_u32(buf + TILE_F), cpt + (size_t)(M_NODES + nbase) * C_CFG, mb1);
    }

    // Root marginals for this block's 64 nodes.
    if (tid < NPB)
        out[nbase + tid] = acc_sigmoid(root[nbase + tid]);
    __syncthreads();   // roots stored + mbarrier init visible
    if (tid == 0) {
        __threadfence();
        atomicAdd(&g_done[0], 1u);
    }

#pragma unroll 1
    for (int l = 0; l < N_LAYERS; l++) {
        float* tb = buf + (l & 1) * TILE_F;
        const uint32_t mb = (l & 1) ? mb1 : mb0;

        // Parent index: thread tid covers node (nbase + tid>>3), parent tid&7
        // == node nloc, parent lane&7 for this warp layout. Coalesced.
        const int pidx =
            parents[(size_t)l * M_NODES * K_PAR + (size_t)nbase * K_PAR + tid];

        // Wait for this layer's CPT tile.
        mbar_wait(mb, (l >> 1) & 1);

        // Wait for previous layer's marginals (release/acquire handoff).
        if (tid == 0) {
            unsigned v;
            do {
                asm volatile("ld.acquire.gpu.global.u32 %0, [%1];"
                             : "=r"(v) : "l"(&g_done[l]) : "memory");
                if (v >= NBLK) break;
                __nanosleep(64);
            } while (true);
        }
        __syncthreads();

        const float* prev = out + (size_t)l * M_NODES;
        float*       dst  = out + (size_t)(l + 1) * M_NODES;
        const float pp = prev[pidx];

        float p[8];
#pragma unroll
        for (int j = 0; j < 8; j++)
            p[j] = __shfl_sync(0xffffffffu, pp, pbase | j);

        float r = fold_node(tb + nloc * C_CFG, p, lane);
        if ((lane & 7) == 0)
            dst[nbase + nloc] = fmaf(0.5f, r, 0.5f);

        __syncthreads();   // all reads of tb done + stores issued
        if (tid == 0) {
            __threadfence();
            atomicAdd(&g_done[l + 1], 1u);      // release outputs
            // Refill the freed buffer with layer l+2's tile.
            if (l + 2 < N_LAYERS)
                tma_tile(smem_u32(tb),
                         cpt + ((size_t)(l + 2) * M_NODES + nbase) * C_CFG, mb);
        }
    }

    // Replay-safe counter reset (ordered after all fenced signals).
    if (blockIdx.x == 0 && tid == 0) {
        unsigned v;
        do {
            asm volatile("ld.acquire.gpu.global.u32 %0, [%1];"
                         : "=r"(v) : "l"(&g_done[N_LAYERS]) : "memory");
            if (v >= NBLK) break;
            __nanosleep(64);
        } while (true);
#pragma unroll
        for (int i = 0; i <= N_LAYERS; i++)
            g_done[i] = 0;
        __threadfence();
    }
}

extern "C" void kernel_launch(void* const* d_in, const int* in_sizes, int n_in,
                              void* d_out, int out_size) {
    const float* root    = (const float*)d_in[0];  // [M]
    const float* cpt     = (const float*)d_in[1];  // [L, M, C]
    const int*   parents = (const int*)  d_in[2];  // [L, M, K]
    float*       out     = (float*)d_out;          // [(L+1)*M]

    static const int SMEM_DYN = 2 * TILE_B;        // 128 KB
    cudaFuncSetAttribute(persist_kernel,
                         cudaFuncAttributeMaxDynamicSharedMemorySize, SMEM_DYN);

    persist_kernel<<<NBLK, TPB, SMEM_DYN>>>(root, cpt, parents, out);
}